// round 15
// baseline (speedup 1.0000x reference)
#include <cuda_runtime.h>
#include <math.h>

typedef unsigned long long ull;
typedef unsigned int uint;

#define B_    64
#define NDML  6000
#define DF    512
#define P_    24960
#define DIM   2048
#define KNN   10

// scratch (device globals; no allocation)
__device__ float g_dmlnorm[NDML];
__device__ float g_clspart[32 * B_ * DF];
__device__ float g_cls[B_ * DF];
__device__ float g_scorepart[6 * B_ * NDML];
__device__ int   g_idx[B_ * KNN];
__device__ float g_embed[B_ * P_];
__device__ float g_qpart[27 * B_ * DIM];
__device__ float g_q[B_ * DIM];
__device__ float g_t[B_ * P_];
__device__ float g_spart[12 * B_ * 20];
__device__ float g_attn[B_ * 20];
__device__ float g_xT[3072 * B_];
__device__ float g_clsT[DF * B_];

__device__ __forceinline__ ull fma2(ull a, ull b, ull c) {
    ull d; asm("fma.rn.f32x2 %0, %1, %2, %3;" : "=l"(d) : "l"(a), "l"(b), "l"(c)); return d;
}
__device__ __forceinline__ ull pk2(float v) {
    ull r; uint u = __float_as_uint(v);
    asm("mov.b64 %0, {%1, %2};" : "=l"(r) : "r"(u), "r"(u)); return r;
}
__device__ __forceinline__ float2 up2(ull v) {
    uint lo, hi; asm("mov.b64 {%0, %1}, %2;" : "=r"(lo), "=r"(hi) : "l"(v));
    return make_float2(__uint_as_float(lo), __uint_as_float(hi));
}
__device__ __forceinline__ unsigned s2u(const void* p) {
    return (unsigned)__cvta_generic_to_shared(p);
}
__device__ __forceinline__ void cp16(unsigned dst, const void* src) {
    asm volatile("cp.async.cg.shared.global [%0], [%1], 16;" :: "r"(dst), "l"(src));
}
#define CPCOMMIT() asm volatile("cp.async.commit_group;")
#define CPWAIT1()  asm volatile("cp.async.wait_group 1;")
#define CPWAIT0()  asm volatile("cp.async.wait_group 0;")

__device__ __forceinline__ uint cvtpack(float lo, float hi) {
    uint r; asm("cvt.rn.bf16x2.f32 %0, %1, %2;" : "=r"(r) : "f"(hi), "f"(lo)); return r;
}

#define LDSM4(r, a) \
    asm volatile("ldmatrix.sync.aligned.m8n8.x4.shared.b16 {%0,%1,%2,%3}, [%4];" \
        : "=r"((r)[0]), "=r"((r)[1]), "=r"((r)[2]), "=r"((r)[3]) : "r"(a))
#define LDSM4T(r, a) \
    asm volatile("ldmatrix.sync.aligned.m8n8.x4.trans.shared.b16 {%0,%1,%2,%3}, [%4];" \
        : "=r"((r)[0]), "=r"((r)[1]), "=r"((r)[2]), "=r"((r)[3]) : "r"(a))

#define MMA16816(d, A, bb0, bb1) \
    asm volatile("mma.sync.aligned.m16n8k16.row.col.f32.bf16.bf16.f32 " \
        "{%0,%1,%2,%3},{%4,%5,%6,%7},{%8,%9},{%0,%1,%2,%3};" \
        : "+f"((d)[0]), "+f"((d)[1]), "+f"((d)[2]), "+f"((d)[3]) \
        : "r"((A)[0]), "r"((A)[1]), "r"((A)[2]), "r"((A)[3]), "r"(bb0), "r"(bb1))

#define CVTSTS(v, hoff, loff) { \
    uint h0 = cvtpack((v).x, (v).y), h1 = cvtpack((v).z, (v).w); \
    float rx = (v).x - __uint_as_float(h0 << 16); \
    float ry = (v).y - __uint_as_float(h0 & 0xffff0000u); \
    float rz = (v).z - __uint_as_float(h1 << 16); \
    float rw = (v).w - __uint_as_float(h1 & 0xffff0000u); \
    uint l0 = cvtpack(rx, ry), l1 = cvtpack(rz, rw); \
    asm volatile("st.shared.v2.u32 [%0], {%1, %2};" :: "r"(sb + (hoff)), "r"(h0), "r"(h1)); \
    asm volatile("st.shared.v2.u32 [%0], {%1, %2};" :: "r"(sb + (loff)), "r"(l0), "r"(l1)); }

// ============ t = q @ Wk^T (NT, mma.sync bf16x3), 2 CTAs/SM ============
__global__ __launch_bounds__(256, 2) void tmma_k(const float* __restrict__ q,
                                                 const float* __restrict__ Wk,
                                                 float* __restrict__ tout)
{
    extern __shared__ __align__(1024) char smem[];
    const int AH = 0, AL = 8192, BH = 16384, BL = 32768;
    uint sb = s2u(smem);
    const int t = threadIdx.x, lane = t & 31, wid = t >> 5;
    const int wm = wid & 1, wn = wid >> 1;
    const int p0 = blockIdx.x * 128;

    float acc[2][4][4];
#pragma unroll
    for (int a = 0; a < 2; a++)
#pragma unroll
        for (int b = 0; b < 4; b++)
#pragma unroll
            for (int c = 0; c < 4; c++) acc[a][b][c] = 0.f;

    float4 rb[4], ra0[4];
    const int ar = t >> 4, ak = t & 15;          // A/B row-col decode (128B rows)
#define T_LDA(s) { const float* qb = q + (s) * 64; \
    _Pragma("unroll") \
    for (int i = 0; i < 4; i++) { int idx = t + i * 256; int r = idx >> 4, k4 = idx & 15; \
        rb[i] = *(const float4*)(qb + (size_t)r * DIM + k4 * 4); } }
#define T_LDB0(s) { const float* wkb = Wk + (size_t)p0 * DIM + (s) * 64; \
    _Pragma("unroll") \
    for (int i = 0; i < 4; i++) { int idx = t + i * 256; int r = idx >> 4, k4 = idx & 15; \
        ra0[i] = *(const float4*)(wkb + (size_t)r * DIM + k4 * 4); } }

    T_LDA(0); T_LDB0(0);
    for (int s = 0; s < 32; s++) {
        float4 ra1[4];
        {   const float* wkb = Wk + (size_t)p0 * DIM + s * 64;
#pragma unroll
            for (int i = 4; i < 8; i++) { int idx = t + i * 256; int r = idx >> 4, k4 = idx & 15;
                ra1[i - 4] = *(const float4*)(wkb + (size_t)r * DIM + k4 * 4); }
        }
        __syncthreads();
#pragma unroll
        for (int i = 0; i < 4; i++) {          // A = q
            int idx = t + i * 256; int r = idx >> 4, k4 = idx & 15;
            uint bo = r * 128 + k4 * 8; uint sw = bo ^ ((bo >> 3) & 0x70);
            CVTSTS(rb[i], AH + sw, AL + sw);
        }
#pragma unroll
        for (int i = 0; i < 4; i++) {          // B half0 (rows 0..63)
            int idx = t + i * 256; int r = idx >> 4, k4 = idx & 15;
            uint bo = r * 128 + k4 * 8; uint sw = bo ^ ((bo >> 3) & 0x70);
            CVTSTS(ra0[i], BH + sw, BL + sw);
        }
#pragma unroll
        for (int i = 4; i < 8; i++) {          // B half1 (rows 64..127)
            int idx = t + i * 256; int r = idx >> 4, k4 = idx & 15;
            uint bo = r * 128 + k4 * 8; uint sw = bo ^ ((bo >> 3) & 0x70);
            CVTSTS(ra1[i - 4], BH + sw, BL + sw);
        }
        __syncthreads();
        if (s + 1 < 32) { T_LDA(s + 1); T_LDB0(s + 1); }

#pragma unroll
        for (int ks = 0; ks < 4; ks++) {
            const int rbase = lane & 15;
            const int kb = ks * 32 + ((lane >> 4) << 4);
            uint ah[2][4], al[2][4], bh[2][4], bl[2][4];
#pragma unroll
            for (int mt = 0; mt < 2; mt++) {
                int row = wm * 32 + mt * 16 + rbase;
                uint bo = row * 128 + kb; uint sw = bo ^ ((bo >> 3) & 0x70);
                LDSM4(ah[mt], sb + AH + sw);
                LDSM4(al[mt], sb + AL + sw);
            }
#pragma unroll
            for (int nb = 0; nb < 2; nb++) {
                int row = wn * 32 + nb * 16 + rbase;
                uint bo = row * 128 + kb; uint sw = bo ^ ((bo >> 3) & 0x70);
                LDSM4(bh[nb], sb + BH + sw);
                LDSM4(bl[nb], sb + BL + sw);
            }
#pragma unroll
            for (int mt = 0; mt < 2; mt++)
#pragma unroll
                for (int nb = 0; nb < 2; nb++)
#pragma unroll
                    for (int sub = 0; sub < 2; sub++) {
                        float* d = acc[mt][nb * 2 + sub];
                        MMA16816(d, ah[mt], bh[nb][sub], bh[nb][sub + 2]);
                        MMA16816(d, al[mt], bh[nb][sub], bh[nb][sub + 2]);
                        MMA16816(d, ah[mt], bl[nb][sub], bl[nb][sub + 2]);
                    }
        }
    }

    const int rg = lane >> 2, tg = lane & 3;
#pragma unroll
    for (int mt = 0; mt < 2; mt++)
#pragma unroll
        for (int j = 0; j < 4; j++) {
            int m = wm * 32 + mt * 16 + rg;
            int col = p0 + wn * 32 + j * 8 + tg * 2;
            *(float2*)&tout[(size_t)m * P_ + col] = make_float2(acc[mt][j][0], acc[mt][j][1]);
            *(float2*)&tout[(size_t)(m + 8) * P_ + col] = make_float2(acc[mt][j][2], acc[mt][j][3]);
        }
}

// ============ qpart[split][64][2048] = embed @ Wq (NN, mma.sync bf16x3), 2 CTAs/SM ============
// Split-K 13 x 1920 (30 chunks of 64); grid 16x13 = 208 CTAs = single resident wave.
__global__ __launch_bounds__(256, 2) void qmma_k(const float* __restrict__ embed,
                                                 const float* __restrict__ Wq,
                                                 float* __restrict__ qpart)
{
    extern __shared__ __align__(1024) char smem[];
    const int AH = 0, AL = 8192, BH = 16384, BL = 32768;
    uint sb = s2u(smem);
    const int t = threadIdx.x, lane = t & 31, wid = t >> 5;
    const int wm = wid & 1, wn = wid >> 1;
    const int n0 = blockIdx.x * 128;
    const int kbase = blockIdx.y * 1920;

    float acc[2][4][4];
#pragma unroll
    for (int a = 0; a < 2; a++)
#pragma unroll
        for (int b = 0; b < 4; b++)
#pragma unroll
            for (int c = 0; c < 4; c++) acc[a][b][c] = 0.f;

    float4 rb[4], ra0[4];
#define Q_LDA(s) { int kb = kbase + (s) * 64; \
    _Pragma("unroll") \
    for (int i = 0; i < 4; i++) { int idx = t + i * 256; int r = idx >> 4, k4 = idx & 15; \
        rb[i] = *(const float4*)(embed + (size_t)r * P_ + kb + k4 * 4); } }
#define Q_LDB0(s) { int kb = kbase + (s) * 64; \
    _Pragma("unroll") \
    for (int i = 0; i < 4; i++) { int idx = t + i * 256; int r = idx >> 5, c = idx & 31; \
        ra0[i] = *(const float4*)(Wq + (size_t)(kb + r) * DIM + n0 + c * 4); } }

    Q_LDA(0); Q_LDB0(0);
    for (int s = 0; s < 30; s++) {
        float4 ra1[4];
        {   int kb = kbase + s * 64;
#pragma unroll
            for (int i = 4; i < 8; i++) { int idx = t + i * 256; int r = idx >> 5, c = idx & 31;
                ra1[i - 4] = *(const float4*)(Wq + (size_t)(kb + r) * DIM + n0 + c * 4); }
        }
        __syncthreads();
#pragma unroll
        for (int i = 0; i < 4; i++) {          // A = embed, 128B rows, SW128
            int idx = t + i * 256; int r = idx >> 4, k4 = idx & 15;
            uint bo = r * 128 + k4 * 8; uint sw = bo ^ ((bo >> 3) & 0x70);
            CVTSTS(rb[i], AH + sw, AL + sw);
        }
#pragma unroll
        for (int i = 0; i < 4; i++) {          // B half0 (k-rows 0..31), 256B rows
            int idx = t + i * 256; int r = idx >> 5, c = idx & 31;
            uint bo = r * 256 + c * 8; uint sw = bo ^ (((bo >> 8) & 7) << 4);
            CVTSTS(ra0[i], BH + sw, BL + sw);
        }
#pragma unroll
        for (int i = 4; i < 8; i++) {          // B half1 (k-rows 32..63)
            int idx = t + i * 256; int r = idx >> 5, c = idx & 31;
            uint bo = r * 256 + c * 8; uint sw = bo ^ (((bo >> 8) & 7) << 4);
            CVTSTS(ra1[i - 4], BH + sw, BL + sw);
        }
        __syncthreads();
        if (s + 1 < 30) { Q_LDA(s + 1); Q_LDB0(s + 1); }

#pragma unroll
        for (int ks = 0; ks < 4; ks++) {
            uint ah[2][4], al[2][4], bh[2][4], bl[2][4];
            const int rbase = lane & 15;
#pragma unroll
            for (int mt = 0; mt < 2; mt++) {
                int row = wm * 32 + mt * 16 + rbase;
                uint bo = row * 128 + ks * 32 + ((lane >> 4) << 4);
                uint sw = bo ^ ((bo >> 3) & 0x70);
                LDSM4(ah[mt], sb + AH + sw);
                LDSM4(al[mt], sb + AL + sw);
            }
#pragma unroll
            for (int nb = 0; nb < 2; nb++) {
                int krow = ks * 16 + rbase;
                int ncol = wn * 32 + nb * 16 + 8 * (lane >> 4);
                uint bo = krow * 256 + ncol * 2;
                uint sw = bo ^ (((bo >> 8) & 7) << 4);
                LDSM4T(bh[nb], sb + BH + sw);
                LDSM4T(bl[nb], sb + BL + sw);
            }
#pragma unroll
            for (int mt = 0; mt < 2; mt++)
#pragma unroll
                for (int nb = 0; nb < 2; nb++)
#pragma unroll
                    for (int sub = 0; sub < 2; sub++) {
                        float* d = acc[mt][nb * 2 + sub];
                        MMA16816(d, ah[mt], bh[nb][2*sub], bh[nb][2*sub+1]);
                        MMA16816(d, al[mt], bh[nb][2*sub], bh[nb][2*sub+1]);
                        MMA16816(d, ah[mt], bl[nb][2*sub], bl[nb][2*sub+1]);
                    }
        }
    }

    float* cp = qpart + (size_t)blockIdx.y * (B_ * DIM);
    const int rg = lane >> 2, tg = lane & 3;
#pragma unroll
    for (int mt = 0; mt < 2; mt++)
#pragma unroll
        for (int j = 0; j < 4; j++) {
            int m = wm * 32 + mt * 16 + rg;
            int col = n0 + wn * 32 + j * 8 + tg * 2;
            *(float2*)&cp[(size_t)m * DIM + col] = make_float2(acc[mt][j][0], acc[mt][j][1]);
            *(float2*)&cp[(size_t)(m + 8) * DIM + col] = make_float2(acc[mt][j][2], acc[mt][j][3]);
        }
}

// ===================== FFMA2 GEMMs (retrieval chain) =====================
template<int BSTRIDE>
__device__ __forceinline__ void mma_step(const float* __restrict__ as,
                                         const float* __restrict__ bs,
                                         int tn, int tb, ull acc[4][4])
{
#pragma unroll 8
    for (int kk = 0; kk < 32; kk++) {
        float4 w = *(const float4*)&bs[kk * BSTRIDE + tn * 4];
        ull w0 = pk2(w.x), w1 = pk2(w.y), w2 = pk2(w.z), w3 = pk2(w.w);
        const ulonglong2* ep = (const ulonglong2*)&as[kk * 64 + tb * 8];
        ulonglong2 ea = ep[0], eb = ep[1];
        ull e0 = ea.x, e1 = ea.y, e2 = eb.x, e3 = eb.y;
        acc[0][0]=fma2(e0,w0,acc[0][0]); acc[0][1]=fma2(e0,w1,acc[0][1]);
        acc[0][2]=fma2(e0,w2,acc[0][2]); acc[0][3]=fma2(e0,w3,acc[0][3]);
        acc[1][0]=fma2(e1,w0,acc[1][0]); acc[1][1]=fma2(e1,w1,acc[1][1]);
        acc[1][2]=fma2(e1,w2,acc[1][2]); acc[1][3]=fma2(e1,w3,acc[1][3]);
        acc[2][0]=fma2(e2,w0,acc[2][0]); acc[2][1]=fma2(e2,w1,acc[2][1]);
        acc[2][2]=fma2(e2,w2,acc[2][2]); acc[2][3]=fma2(e2,w3,acc[2][3]);
        acc[3][0]=fma2(e3,w0,acc[3][0]); acc[3][1]=fma2(e3,w1,acc[3][1]);
        acc[3][2]=fma2(e3,w2,acc[3][2]); acc[3][3]=fma2(e3,w3,acc[3][3]);
    }
}

__global__ void transpose64(const float* __restrict__ in, float* __restrict__ out, int K)
{
    __shared__ float tile[32][33];
    int k0 = blockIdx.x * 32, b0 = blockIdx.y * 32;
    int tx = threadIdx.x, ty = threadIdx.y;
    tile[ty][tx] = in[(size_t)(b0 + ty) * K + k0 + tx];
    __syncthreads();
    out[(size_t)(k0 + ty) * 64 + b0 + tx] = tile[tx][ty];
}

__global__ __launch_bounds__(256) void gemm_nn(const float* __restrict__ AT,
                                               const float* __restrict__ Bm,
                                               float* __restrict__ Cpart,
                                               int N, int K, int kchunk)
{
    extern __shared__ __align__(16) float sm[];
    float* Asb = sm;
    float* Bsb = sm + 3 * 2048;
    const int t = threadIdx.x, tn = t & 31, tb = t >> 5;
    const int n0 = blockIdx.x * 128;
    const int k0 = blockIdx.y * kchunk;
    const int kend = min(k0 + kchunk, K);
    const int S = (kend - k0) / 32;

    ull acc[4][4];
#pragma unroll
    for (int j = 0; j < 4; j++)
#pragma unroll
        for (int i = 0; i < 4; i++) acc[j][i] = 0ull;

    const int ar = t >> 4, ac = (t & 15) * 4;
    const int br = t >> 5, bc = (t & 31) * 4;
#define NN_ISSUE(s, buf) { \
    int kb = k0 + (s) * 32; \
    float* Ab = Asb + (buf) * 2048; float* Bb = Bsb + (buf) * 4096; \
    cp16(s2u(Ab + ar * 64 + ac),        AT + (size_t)(kb + ar) * 64 + ac); \
    cp16(s2u(Ab + (ar + 16) * 64 + ac), AT + (size_t)(kb + ar + 16) * 64 + ac); \
    cp16(s2u(Bb + br * 128 + bc),        Bm + (size_t)(kb + br) * N + n0 + bc); \
    cp16(s2u(Bb + (br + 8) * 128 + bc),  Bm + (size_t)(kb + br + 8) * N + n0 + bc); \
    cp16(s2u(Bb + (br + 16) * 128 + bc), Bm + (size_t)(kb + br + 16) * N + n0 + bc); \
    cp16(s2u(Bb + (br + 24) * 128 + bc), Bm + (size_t)(kb + br + 24) * N + n0 + bc); \
    CPCOMMIT(); }

    if (S > 0) NN_ISSUE(0, 0);
    if (S > 1) NN_ISSUE(1, 1);

    for (int s = 0; s < S; s++) {
        const int buf = s % 3;
        if (s + 1 < S) { CPWAIT1(); } else { CPWAIT0(); }
        __syncthreads();
        if (s + 2 < S) NN_ISSUE(s + 2, (s + 2) % 3);
        mma_step<128>(Asb + buf * 2048, Bsb + buf * 4096, tn, tb, acc);
    }

    float* cp = Cpart + (size_t)blockIdx.y * ((size_t)B_ * N);
#pragma unroll
    for (int j = 0; j < 4; j++) {
        float2 u0 = up2(acc[j][0]), u1 = up2(acc[j][1]), u2 = up2(acc[j][2]), u3 = up2(acc[j][3]);
        int be = tb * 8 + 2 * j;
        *(float4*)&cp[(size_t)be * N + n0 + tn * 4]       = make_float4(u0.x, u1.x, u2.x, u3.x);
        *(float4*)&cp[(size_t)(be + 1) * N + n0 + tn * 4] = make_float4(u0.y, u1.y, u2.y, u3.y);
    }
}

__global__ __launch_bounds__(256) void gemm_nt(const float* __restrict__ AT,
                                               const float* __restrict__ Bt,
                                               float* __restrict__ Cpart,
                                               int P, int KD, int kchunk)
{
    extern __shared__ __align__(16) float sm[];
    float* Asb = sm;
    float* Wsb = sm + 3 * 2048;
    const int t = threadIdx.x, tn = t & 31, tb = t >> 5;
    const int p0 = blockIdx.x * 128;
    const int k0 = blockIdx.y * kchunk;
    const int kend = min(k0 + kchunk, KD);
    const int S = (kend - k0) / 32;

    ull acc[4][4];
#pragma unroll
    for (int j = 0; j < 4; j++)
#pragma unroll
        for (int i = 0; i < 4; i++) acc[j][i] = 0ull;

    const int ar = t >> 4, ac = (t & 15) * 4;
    const int lp = t >> 3, l8 = t & 7;
    float4 brg[4];

#define NT_ISSUEA(s, buf) { \
    int kb = k0 + (s) * 32; \
    float* Ab = Asb + (buf) * 2048; \
    cp16(s2u(Ab + ar * 64 + ac),        AT + (size_t)(kb + ar) * 64 + ac); \
    cp16(s2u(Ab + (ar + 16) * 64 + ac), AT + (size_t)(kb + ar + 16) * 64 + ac); \
    CPCOMMIT(); }

#define NT_LDGB(s) { \
    int kb = k0 + (s) * 32; \
    _Pragma("unroll") \
    for (int i = 0; i < 4; i++) { \
        int pg = p0 + lp + i * 32; \
        brg[i] = (pg < P) ? *(const float4*)(Bt + (size_t)pg * KD + kb + l8 * 4) \
                          : make_float4(0.f, 0.f, 0.f, 0.f); \
    } }

#define NT_STSB(buf) { \
    float* Wb = Wsb + (buf) * 4224; \
    _Pragma("unroll") \
    for (int i = 0; i < 4; i++) { \
        int pr = lp + i * 32; \
        Wb[(l8 * 4 + 0) * 132 + pr] = brg[i].x; \
        Wb[(l8 * 4 + 1) * 132 + pr] = brg[i].y; \
        Wb[(l8 * 4 + 2) * 132 + pr] = brg[i].z; \
        Wb[(l8 * 4 + 3) * 132 + pr] = brg[i].w; \
    } }

    if (S > 0) { NT_ISSUEA(0, 0); NT_LDGB(0); NT_STSB(0); }
    if (S > 1) NT_ISSUEA(1, 1);

    for (int s = 0; s < S; s++) {
        const int buf = s % 3;
        if (s + 1 < S) { CPWAIT1(); } else { CPWAIT0(); }
        __syncthreads();
        if (s + 2 < S) NT_ISSUEA(s + 2, (s + 2) % 3);
        if (s + 1 < S) NT_LDGB(s + 1);
        mma_step<132>(Asb + buf * 2048, Wsb + buf * 4224, tn, tb, acc);
        if (s + 1 < S) NT_STSB((s + 1) % 3);
    }

    float* cp = Cpart + (size_t)blockIdx.y * ((size_t)B_ * P);
    int p = p0 + tn * 4;
    if (p < P) {
#pragma unroll
        for (int j = 0; j < 4; j++) {
            float2 u0 = up2(acc[j][0]), u1 = up2(acc[j][1]), u2 = up2(acc[j][2]), u3 = up2(acc[j][3]);
            int be = tb * 8 + 2 * j;
            *(float4*)&cp[(size_t)be * P + p]       = make_float4(u0.x, u1.x, u2.x, u3.x);
            *(float4*)&cp[(size_t)(be + 1) * P + p] = make_float4(u0.y, u1.y, u2.y, u3.y);
        }
    }
}

__global__ void reduce_k(const float* __restrict__ part, float* __restrict__ out, int S, int len4)
{
    int i = blockIdx.x * blockDim.x + threadIdx.x;
    if (i >= len4) return;
    const float4* p4 = (const float4*)part;
    float4 s = p4[i];
    for (int ss = 1; ss < S; ss++) {
        float4 v = p4[(size_t)ss * len4 + i];
        s.x += v.x; s.y += v.y; s.z += v.z; s.w += v.w;
    }
    ((float4*)out)[i] = s;
}

__global__ void dmlnorm_k(const float* __restrict__ dml, float* __restrict__ dn)
{
    int w = threadIdx.x >> 5, lane = threadIdx.x & 31;
    int r = blockIdx.x * 8 + w;
    const float4* row = (const float4*)(dml + (size_t)r * DF);
    float s = 0.f;
#pragma unroll
    for (int i = 0; i < 4; i++) {
        float4 v = row[lane + i * 32];
        s += v.x*v.x + v.y*v.y + v.z*v.z + v.w*v.w;
    }
    for (int off = 16; off; off >>= 1) s += __shfl_down_sync(0xffffffffu, s, off);
    if (lane == 0) dn[r] = s;
}

__global__ void topk_k(const float* __restrict__ spart, const float* __restrict__ dnorm,
                       int* __restrict__ idxo)
{
    int b = blockIdx.x, t = threadIdx.x;
    __shared__ float sv[NDML];
    __shared__ ull red[256];
    for (int j = t; j < NDML; j += 256) {
        float dot = 0.f;
#pragma unroll
        for (int s = 0; s < 6; s++) dot += spart[(size_t)s * (B_ * NDML) + b * NDML + j];
        sv[j] = dnorm[j] - 2.f * dot;
    }
    __syncthreads();
    for (int r = 0; r < KNN; r++) {
        ull best = ~0ull;
        for (int j = t; j < NDML; j += 256) {
            uint u = __float_as_uint(sv[j]);
            u = (u & 0x80000000u) ? ~u : (u | 0x80000000u);
            ull key = ((ull)u << 32) | (uint)j;
            if (key < best) best = key;
        }
        red[t] = best;
        __syncthreads();
        for (int off = 128; off; off >>= 1) {
            if (t < off) { if (red[t + off] < red[t]) red[t] = red[t + off]; }
            __syncthreads();
        }
        int jw = (int)(red[0] & 0xffffffffu);
        if (t == 0) { idxo[b * KNN + r] = jw; sv[jw] = 3.4e38f; }
        __syncthreads();
    }
}

__global__ void embed_k(const float* __restrict__ x, const float* __restrict__ Wp,
                        const float* __restrict__ clst, float* __restrict__ E)
{
    int tok = blockIdx.x, b = blockIdx.y, h = threadIdx.x;
    if (tok == 0) { E[(size_t)b * P_ + h] = clst[h]; return; }
    __shared__ float pn[48];
    int pt = tok - 1, gr = pt >> 3, gc = pt & 7;
    if (h < 48) {
        int c = h >> 4, rem = h & 15, pr = rem >> 2, pc = rem & 3;
        float mean = (c == 0) ? 0.4914f : ((c == 1) ? 0.4822f : 0.4465f);
        float inv  = (c == 0) ? 4.048582995951417f : ((c == 1) ? 4.106776180698152f : 3.822629969418960f);
        float v = x[(((size_t)b * 3 + c) * 32 + gr * 4 + pr) * 32 + gc * 4 + pc];
        pn[h] = (v - mean) * inv;
    }
    __syncthreads();
    float acc = 0.f;
#pragma unroll
    for (int f = 0; f < 48; f++) acc += pn[f] * Wp[f * 384 + h];
    E[(size_t)b * P_ + tok * 384 + h] = acc;
}

__global__ __launch_bounds__(256) void scores_k(const float* __restrict__ tin,
                                                const float* __restrict__ OTin,
                                                const float* __restrict__ OTout,
                                                const int* __restrict__ idx,
                                                float* __restrict__ spart)
{
    int c = blockIdx.x, b = blockIdx.y, t = threadIdx.x;
    __shared__ __align__(16) float ts[2080];
    __shared__ int ids[10];
    __shared__ float warr[8];
    int base4 = (b * P_ + c * 2080) >> 2;
    const float4* t0 = (const float4*)tin + base4;
    for (int i = t; i < 520; i += 256) ((float4*)ts)[i] = t0[i];
    if (t < 10) ids[t] = idx[b * 10 + t];
    __syncthreads();

    float pacc[20];
#pragma unroll
    for (int n = 0; n < 20; n++) pacc[n] = 0.f;
#pragma unroll 1
    for (int n = 0; n < 20; n++) {
        const float* row = ((n < 10) ? OTin : OTout) + (size_t)ids[n % 10] * P_ + c * 2080;
        const float4* r4 = (const float4*)row;
        float s = 0.f;
        for (int i = t; i < 520; i += 256) {
            float4 v = r4[i]; float4 tt = ((float4*)ts)[i];
            s += v.x * tt.x + v.y * tt.y + v.z * tt.z + v.w * tt.w;
        }
        pacc[n] = s;
    }
    int lane = t & 31, wid = t >> 5;
    for (int n = 0; n < 20; n++) {
        float v = pacc[n];
        for (int off = 16; off; off >>= 1) v += __shfl_down_sync(0xffffffffu, v, off);
        if (lane == 0) warr[wid] = v;
        __syncthreads();
        if (t == 0) {
            float s = 0.f;
            for (int w = 0; w < 8; w++) s += warr[w];
            spart[((size_t)c * B_ + b) * 20 + n] = s;
        }
        __syncthreads();
    }
}

__global__ void softmax_k(const float* __restrict__ spart, float* __restrict__ attn)
{
    int b = blockIdx.x, n = threadIdx.x;
    float s = -3.4e38f;
    if (n < 20) {
        float acc = 0.f;
        for (int c = 0; c < 12; c++) acc += spart[((size_t)c * B_ + b) * 20 + n];
        s = acc * 0.022097086912079608f;
    }
    float m = s;
    for (int off = 16; off; off >>= 1) m = fmaxf(m, __shfl_xor_sync(0xffffffffu, m, off));
    float e = (n < 20) ? expf(s - m) : 0.f;
    float sum = e;
    for (int off = 16; off; off >>= 1) sum += __shfl_xor_sync(0xffffffffu, sum, off);
    if (n < 20) attn[b * 20 + n] = e / sum;
}

__global__ __launch_bounds__(256) void out_k(const float* __restrict__ OTin,
                                             const float* __restrict__ OTout,
                                             const int* __restrict__ idx,
                                             const float* __restrict__ attn,
                                             float* __restrict__ out)
{
    int c = blockIdx.x, b = blockIdx.y, t = threadIdx.x;
    __shared__ float a[20];
    __shared__ int ids[10];
    if (t < 20) a[t] = attn[b * 20 + t];
    if (t < 10) ids[t] = idx[b * 10 + t];
    __syncthreads();
    const float4* rows[20];
#pragma unroll
    for (int n = 0; n < 20; n++)
        rows[n] = (const float4*)(((n < 10) ? OTin : OTout) + (size_t)ids[n % 10] * P_ + c * 2080);
    float4* o4 = (float4*)(out + (size_t)b * P_ + c * 2080);
    for (int i = t; i < 520; i += 256) {
        float4 s = make_float4(0.f, 0.f, 0.f, 0.f);
#pragma unroll
        for (int n = 0; n < 20; n++) {
            float4 v = rows[n][i]; float an = a[n];
            s.x += an * v.x; s.y += an * v.y; s.z += an * v.z; s.w += an * v.w;
        }
        o4[i] = s;
    }
}

extern "C" void kernel_launch(void* const* d_in, const int* in_sizes, int n_in,
                              void* d_out, int out_size)
{
    const float* x     = (const float*)d_in[0];
    const float* dml   = (const float*)d_in[1];
    const float* OTin  = (const float*)d_in[2];
    const float* OTout = (const float*)d_in[3];
    const float* Wdml  = (const float*)d_in[4];
    const float* Wp    = (const float*)d_in[5];
    const float* clst  = (const float*)d_in[6];
    const float* Wq    = (const float*)d_in[7];
    const float* Wk    = (const float*)d_in[8];
    float* out = (float*)d_out;

    float *clspart, *cls, *dnorm, *scorepart, *embed, *qpart, *q, *tbuf, *spart, *attn;
    float *xT, *clsT;
    int* idx;
    cudaGetSymbolAddress((void**)&clspart,  g_clspart);
    cudaGetSymbolAddress((void**)&cls,      g_cls);
    cudaGetSymbolAddress((void**)&dnorm,    g_dmlnorm);
    cudaGetSymbolAddress((void**)&scorepart,g_scorepart);
    cudaGetSymbolAddress((void**)&idx,      g_idx);
    cudaGetSymbolAddress((void**)&embed,    g_embed);
    cudaGetSymbolAddress((void**)&qpart,    g_qpart);
    cudaGetSymbolAddress((void**)&q,        g_q);
    cudaGetSymbolAddress((void**)&tbuf,     g_t);
    cudaGetSymbolAddress((void**)&spart,    g_spart);
    cudaGetSymbolAddress((void**)&attn,     g_attn);
    cudaGetSymbolAddress((void**)&xT,       g_xT);
    cudaGetSymbolAddress((void**)&clsT,     g_clsT);

    const int nn_smem = (3 * 2048 + 3 * 4096) * 4;
    const int nt_smem = (3 * 2048 + 3 * 4224) * 4;
    const int tm_smem = 49152;
    cudaFuncSetAttribute(gemm_nn, cudaFuncAttributeMaxDynamicSharedMemorySize, nn_smem);
    cudaFuncSetAttribute(gemm_nt, cudaFuncAttributeMaxDynamicSharedMemorySize, nt_smem);
    cudaFuncSetAttribute(tmma_k, cudaFuncAttributeMaxDynamicSharedMemorySize, tm_smem);
    cudaFuncSetAttribute(qmma_k, cudaFuncAttributeMaxDynamicSharedMemorySize, tm_smem);

    dim3 t32(32, 32);
    embed_k<<<dim3(65, 64), 384>>>(x, Wp, clst, embed);                // 1
    dmlnorm_k<<<750, 256>>>(dml, dnorm);                               // 2
    transpose64<<<dim3(96, 2), t32>>>(x, xT, 3072);                    // 3
    qmma_k<<<dim3(16, 13), 256, tm_smem>>>(embed, Wq, qpart);          // 4 (profiled)
    reduce_k<<<128, 256>>>(qpart, q, 13, (B_ * DIM) / 4);              // 5
    tmma_k<<<195, 256, tm_smem>>>(q, Wk, tbuf);                        // 6
    // retrieval chain
    gemm_nn<<<dim3(4, 32), 256, nn_smem>>>(xT, Wdml, clspart, DF, 3072, 96);
    reduce_k<<<32, 256>>>(clspart, cls, 32, (B_ * DF) / 4);
    transpose64<<<dim3(16, 2), t32>>>(cls, clsT, DF);
    gemm_nt<<<dim3(47, 6), 256, nt_smem>>>(clsT, dml, scorepart, NDML, DF, 96);
    topk_k<<<64, 256>>>(scorepart, dnorm, idx);
    // attention readout
    scores_k<<<dim3(12, 64), 256>>>(tbuf, OTin, OTout, idx, spart);
    softmax_k<<<64, 32>>>(spart, attn);
    out_k<<<dim3(12, 64), 256>>>(OTin, OTout, idx, attn, out);
}

// round 16
// speedup vs baseline: 1.0872x; 1.0872x over previous
#include <cuda_runtime.h>
#include <math.h>

typedef unsigned long long ull;
typedef unsigned int uint;

#define B_    64
#define NDML  6000
#define DF    512
#define P_    24960
#define DIM   2048
#define KNN   10

// scratch (device globals; no allocation)
__device__ float g_dmlnorm[NDML];
__device__ float g_clspart[32 * B_ * DF];
__device__ float g_cls[B_ * DF];
__device__ float g_scorepart[6 * B_ * NDML];
__device__ int   g_idx[B_ * KNN];
__device__ float g_embed[B_ * P_];
__device__ float g_qpart[27 * B_ * DIM];
__device__ float g_q[B_ * DIM];
__device__ float g_t[B_ * P_];
__device__ float g_spart[12 * B_ * 20];
__device__ float g_attn[B_ * 20];
__device__ float g_xT[3072 * B_];
__device__ float g_clsT[DF * B_];

__device__ __forceinline__ ull fma2(ull a, ull b, ull c) {
    ull d; asm("fma.rn.f32x2 %0, %1, %2, %3;" : "=l"(d) : "l"(a), "l"(b), "l"(c)); return d;
}
__device__ __forceinline__ ull pk2(float v) {
    ull r; uint u = __float_as_uint(v);
    asm("mov.b64 %0, {%1, %2};" : "=l"(r) : "r"(u), "r"(u)); return r;
}
__device__ __forceinline__ float2 up2(ull v) {
    uint lo, hi; asm("mov.b64 {%0, %1}, %2;" : "=r"(lo), "=r"(hi) : "l"(v));
    return make_float2(__uint_as_float(lo), __uint_as_float(hi));
}
__device__ __forceinline__ unsigned s2u(const void* p) {
    return (unsigned)__cvta_generic_to_shared(p);
}
__device__ __forceinline__ void cp16(unsigned dst, const void* src) {
    asm volatile("cp.async.cg.shared.global [%0], [%1], 16;" :: "r"(dst), "l"(src));
}
#define CPCOMMIT() asm volatile("cp.async.commit_group;")
#define CPWAIT1()  asm volatile("cp.async.wait_group 1;")
#define CPWAIT0()  asm volatile("cp.async.wait_group 0;")

__device__ __forceinline__ uint cvtpack(float lo, float hi) {
    uint r; asm("cvt.rn.bf16x2.f32 %0, %1, %2;" : "=r"(r) : "f"(hi), "f"(lo)); return r;
}

#define LDSM4(r, a) \
    asm volatile("ldmatrix.sync.aligned.m8n8.x4.shared.b16 {%0,%1,%2,%3}, [%4];" \
        : "=r"((r)[0]), "=r"((r)[1]), "=r"((r)[2]), "=r"((r)[3]) : "r"(a))
#define LDSM4T(r, a) \
    asm volatile("ldmatrix.sync.aligned.m8n8.x4.trans.shared.b16 {%0,%1,%2,%3}, [%4];" \
        : "=r"((r)[0]), "=r"((r)[1]), "=r"((r)[2]), "=r"((r)[3]) : "r"(a))

#define MMA16816(d, A, bb0, bb1) \
    asm volatile("mma.sync.aligned.m16n8k16.row.col.f32.bf16.bf16.f32 " \
        "{%0,%1,%2,%3},{%4,%5,%6,%7},{%8,%9},{%0,%1,%2,%3};" \
        : "+f"((d)[0]), "+f"((d)[1]), "+f"((d)[2]), "+f"((d)[3]) \
        : "r"((A)[0]), "r"((A)[1]), "r"((A)[2]), "r"((A)[3]), "r"(bb0), "r"(bb1))

#define CVTSTS(v, hoff, loff) { \
    uint h0 = cvtpack((v).x, (v).y), h1 = cvtpack((v).z, (v).w); \
    float rx = (v).x - __uint_as_float(h0 << 16); \
    float ry = (v).y - __uint_as_float(h0 & 0xffff0000u); \
    float rz = (v).z - __uint_as_float(h1 << 16); \
    float rw = (v).w - __uint_as_float(h1 & 0xffff0000u); \
    uint l0 = cvtpack(rx, ry), l1 = cvtpack(rz, rw); \
    asm volatile("st.shared.v2.u32 [%0], {%1, %2};" :: "r"(sb + (hoff)), "r"(h0), "r"(h1)); \
    asm volatile("st.shared.v2.u32 [%0], {%1, %2};" :: "r"(sb + (loff)), "r"(l0), "r"(l1)); }

// ============ t = q @ Wk^T (NT, mma.sync bf16x3), n-tile 64, 2 CTAs/SM ============
// CTA: 64 Wk rows x full m=64; 32 chunks of k=64. smem 32KB.
__global__ __launch_bounds__(256, 2) void tmma_k(const float* __restrict__ q,
                                                 const float* __restrict__ Wk,
                                                 float* __restrict__ tout)
{
    extern __shared__ __align__(1024) char smem[];
    const int AH = 0, AL = 8192, BH = 16384, BL = 24576;
    uint sb = s2u(smem);
    const int t = threadIdx.x, lane = t & 31, wid = t >> 5;
    const int wm = wid & 1, wn = wid >> 1;          // 2 m-warps x 4 n-warps (16n each)
    const int p0 = blockIdx.x * 64;

    float acc[2][2][4];
#pragma unroll
    for (int a = 0; a < 2; a++)
#pragma unroll
        for (int b = 0; b < 2; b++)
#pragma unroll
            for (int c = 0; c < 4; c++) acc[a][b][c] = 0.f;

    float4 ra[4], rb[4];   // ra = Wk 64x64, rb = q 64x64
#define T_LDG(s) { \
    const float* wkb = Wk + (size_t)p0 * DIM + (s) * 64; \
    const float* qb  = q + (s) * 64; \
    _Pragma("unroll") \
    for (int i = 0; i < 4; i++) { int idx = t + i * 256; int r = idx >> 4, k4 = idx & 15; \
        ra[i] = *(const float4*)(wkb + (size_t)r * DIM + k4 * 4); \
        rb[i] = *(const float4*)(qb  + (size_t)r * DIM + k4 * 4); } }

    T_LDG(0);
    for (int s = 0; s < 32; s++) {
        __syncthreads();
#pragma unroll
        for (int i = 0; i < 4; i++) {
            int idx = t + i * 256; int r = idx >> 4, k4 = idx & 15;
            uint bo = r * 128 + k4 * 8; uint sw = bo ^ ((bo >> 3) & 0x70);
            CVTSTS(rb[i], AH + sw, AL + sw);
            CVTSTS(ra[i], BH + sw, BL + sw);
        }
        __syncthreads();
        if (s + 1 < 32) T_LDG(s + 1);

#pragma unroll
        for (int ks = 0; ks < 4; ks++) {
            const int rbase = lane & 15;
            const int kb = ks * 32 + ((lane >> 4) << 4);
            uint ah[2][4], al[2][4], bh[4], bl[4];
#pragma unroll
            for (int mt = 0; mt < 2; mt++) {
                int row = wm * 32 + mt * 16 + rbase;
                uint bo = row * 128 + kb; uint sw = bo ^ ((bo >> 3) & 0x70);
                LDSM4(ah[mt], sb + AH + sw);
                LDSM4(al[mt], sb + AL + sw);
            }
            {
                int row = wn * 16 + rbase;
                uint bo = row * 128 + kb; uint sw = bo ^ ((bo >> 3) & 0x70);
                LDSM4(bh, sb + BH + sw);
                LDSM4(bl, sb + BL + sw);
            }
#pragma unroll
            for (int mt = 0; mt < 2; mt++)
#pragma unroll
                for (int sub = 0; sub < 2; sub++) {
                    float* d = acc[mt][sub];
                    MMA16816(d, ah[mt], bh[sub], bh[sub + 2]);
                    MMA16816(d, al[mt], bh[sub], bh[sub + 2]);
                    MMA16816(d, ah[mt], bl[sub], bl[sub + 2]);
                }
        }
    }

    const int rg = lane >> 2, tg = lane & 3;
#pragma unroll
    for (int mt = 0; mt < 2; mt++)
#pragma unroll
        for (int j = 0; j < 2; j++) {
            int m = wm * 32 + mt * 16 + rg;
            int col = p0 + wn * 16 + j * 8 + tg * 2;
            *(float2*)&tout[(size_t)m * P_ + col] = make_float2(acc[mt][j][0], acc[mt][j][1]);
            *(float2*)&tout[(size_t)(m + 8) * P_ + col] = make_float2(acc[mt][j][2], acc[mt][j][3]);
        }
}

// ============ qpart[split][64][2048] = embed @ Wq (NN, mma.sync bf16x3), n-tile 64 ============
// Split-K 13 x 1920 (30 chunks of 64); grid 32 x 13 = 416 CTAs. smem 32KB, 2 CTAs/SM.
__global__ __launch_bounds__(256, 2) void qmma_k(const float* __restrict__ embed,
                                                 const float* __restrict__ Wq,
                                                 float* __restrict__ qpart)
{
    extern __shared__ __align__(1024) char smem[];
    const int AH = 0, AL = 8192, BH = 16384, BL = 24576;
    uint sb = s2u(smem);
    const int t = threadIdx.x, lane = t & 31, wid = t >> 5;
    const int wm = wid & 1, wn = wid >> 1;
    const int n0 = blockIdx.x * 64;
    const int kbase = blockIdx.y * 1920;

    float acc[2][2][4];
#pragma unroll
    for (int a = 0; a < 2; a++)
#pragma unroll
        for (int b = 0; b < 2; b++)
#pragma unroll
            for (int c = 0; c < 4; c++) acc[a][b][c] = 0.f;

    float4 ra[4], rb[4];   // ra = Wq 64k x 64n, rb = embed 64x64
#define Q_LDG(s) { \
    int kb = kbase + (s) * 64; \
    _Pragma("unroll") \
    for (int i = 0; i < 4; i++) { int idx = t + i * 256; int r = idx >> 4, c4 = idx & 15; \
        ra[i] = *(const float4*)(Wq + (size_t)(kb + r) * DIM + n0 + c4 * 4); \
        rb[i] = *(const float4*)(embed + (size_t)r * P_ + kb + c4 * 4); } }

    Q_LDG(0);
    for (int s = 0; s < 30; s++) {
        __syncthreads();
#pragma unroll
        for (int i = 0; i < 4; i++) {
            int idx = t + i * 256; int r = idx >> 4, c4 = idx & 15;
            uint bo = r * 128 + c4 * 8; uint sw = bo ^ ((bo >> 3) & 0x70);
            CVTSTS(rb[i], AH + sw, AL + sw);   // A: row=m, col=k (128B rows)
            CVTSTS(ra[i], BH + sw, BL + sw);   // B: row=k, col=n (128B rows)
        }
        __syncthreads();
        if (s + 1 < 30) Q_LDG(s + 1);

#pragma unroll
        for (int ks = 0; ks < 4; ks++) {
            uint ah[2][4], al[2][4], bh[4], bl[4];
            const int rbase = lane & 15;
#pragma unroll
            for (int mt = 0; mt < 2; mt++) {   // A frags (non-trans)
                int row = wm * 32 + mt * 16 + rbase;
                uint bo = row * 128 + ks * 32 + ((lane >> 4) << 4);
                uint sw = bo ^ ((bo >> 3) & 0x70);
                LDSM4(ah[mt], sb + AH + sw);
                LDSM4(al[mt], sb + AL + sw);
            }
            {                                   // B frags (trans): k-row x n-col
                int krow = ks * 16 + rbase;
                int ncol = wn * 16 + 8 * (lane >> 4);
                uint bo = krow * 128 + ncol * 2;
                uint sw = bo ^ ((bo >> 3) & 0x70);
                LDSM4T(bh, sb + BH + sw);
                LDSM4T(bl, sb + BL + sw);
            }
#pragma unroll
            for (int mt = 0; mt < 2; mt++)
#pragma unroll
                for (int sub = 0; sub < 2; sub++) {
                    float* d = acc[mt][sub];
                    MMA16816(d, ah[mt], bh[2*sub], bh[2*sub+1]);
                    MMA16816(d, al[mt], bh[2*sub], bh[2*sub+1]);
                    MMA16816(d, ah[mt], bl[2*sub], bl[2*sub+1]);
                }
        }
    }

    float* cp = qpart + (size_t)blockIdx.y * (B_ * DIM);
    const int rg = lane >> 2, tg = lane & 3;
#pragma unroll
    for (int mt = 0; mt < 2; mt++)
#pragma unroll
        for (int j = 0; j < 2; j++) {
            int m = wm * 32 + mt * 16 + rg;
            int col = n0 + wn * 16 + j * 8 + tg * 2;
            *(float2*)&cp[(size_t)m * DIM + col] = make_float2(acc[mt][j][0], acc[mt][j][1]);
            *(float2*)&cp[(size_t)(m + 8) * DIM + col] = make_float2(acc[mt][j][2], acc[mt][j][3]);
        }
}

// ===================== FFMA2 GEMMs (retrieval chain) =====================
template<int BSTRIDE>
__device__ __forceinline__ void mma_step(const float* __restrict__ as,
                                         const float* __restrict__ bs,
                                         int tn, int tb, ull acc[4][4])
{
#pragma unroll 8
    for (int kk = 0; kk < 32; kk++) {
        float4 w = *(const float4*)&bs[kk * BSTRIDE + tn * 4];
        ull w0 = pk2(w.x), w1 = pk2(w.y), w2 = pk2(w.z), w3 = pk2(w.w);
        const ulonglong2* ep = (const ulonglong2*)&as[kk * 64 + tb * 8];
        ulonglong2 ea = ep[0], eb = ep[1];
        ull e0 = ea.x, e1 = ea.y, e2 = eb.x, e3 = eb.y;
        acc[0][0]=fma2(e0,w0,acc[0][0]); acc[0][1]=fma2(e0,w1,acc[0][1]);
        acc[0][2]=fma2(e0,w2,acc[0][2]); acc[0][3]=fma2(e0,w3,acc[0][3]);
        acc[1][0]=fma2(e1,w0,acc[1][0]); acc[1][1]=fma2(e1,w1,acc[1][1]);
        acc[1][2]=fma2(e1,w2,acc[1][2]); acc[1][3]=fma2(e1,w3,acc[1][3]);
        acc[2][0]=fma2(e2,w0,acc[2][0]); acc[2][1]=fma2(e2,w1,acc[2][1]);
        acc[2][2]=fma2(e2,w2,acc[2][2]); acc[2][3]=fma2(e2,w3,acc[2][3]);
        acc[3][0]=fma2(e3,w0,acc[3][0]); acc[3][1]=fma2(e3,w1,acc[3][1]);
        acc[3][2]=fma2(e3,w2,acc[3][2]); acc[3][3]=fma2(e3,w3,acc[3][3]);
    }
}

__global__ void transpose64(const float* __restrict__ in, float* __restrict__ out, int K)
{
    __shared__ float tile[32][33];
    int k0 = blockIdx.x * 32, b0 = blockIdx.y * 32;
    int tx = threadIdx.x, ty = threadIdx.y;
    tile[ty][tx] = in[(size_t)(b0 + ty) * K + k0 + tx];
    __syncthreads();
    out[(size_t)(k0 + ty) * 64 + b0 + tx] = tile[tx][ty];
}

__global__ __launch_bounds__(256) void gemm_nn(const float* __restrict__ AT,
                                               const float* __restrict__ Bm,
                                               float* __restrict__ Cpart,
                                               int N, int K, int kchunk)
{
    extern __shared__ __align__(16) float sm[];
    float* Asb = sm;
    float* Bsb = sm + 3 * 2048;
    const int t = threadIdx.x, tn = t & 31, tb = t >> 5;
    const int n0 = blockIdx.x * 128;
    const int k0 = blockIdx.y * kchunk;
    const int kend = min(k0 + kchunk, K);
    const int S = (kend - k0) / 32;

    ull acc[4][4];
#pragma unroll
    for (int j = 0; j < 4; j++)
#pragma unroll
        for (int i = 0; i < 4; i++) acc[j][i] = 0ull;

    const int ar = t >> 4, ac = (t & 15) * 4;
    const int br = t >> 5, bc = (t & 31) * 4;
#define NN_ISSUE(s, buf) { \
    int kb = k0 + (s) * 32; \
    float* Ab = Asb + (buf) * 2048; float* Bb = Bsb + (buf) * 4096; \
    cp16(s2u(Ab + ar * 64 + ac),        AT + (size_t)(kb + ar) * 64 + ac); \
    cp16(s2u(Ab + (ar + 16) * 64 + ac), AT + (size_t)(kb + ar + 16) * 64 + ac); \
    cp16(s2u(Bb + br * 128 + bc),        Bm + (size_t)(kb + br) * N + n0 + bc); \
    cp16(s2u(Bb + (br + 8) * 128 + bc),  Bm + (size_t)(kb + br + 8) * N + n0 + bc); \
    cp16(s2u(Bb + (br + 16) * 128 + bc), Bm + (size_t)(kb + br + 16) * N + n0 + bc); \
    cp16(s2u(Bb + (br + 24) * 128 + bc), Bm + (size_t)(kb + br + 24) * N + n0 + bc); \
    CPCOMMIT(); }

    if (S > 0) NN_ISSUE(0, 0);
    if (S > 1) NN_ISSUE(1, 1);

    for (int s = 0; s < S; s++) {
        const int buf = s % 3;
        if (s + 1 < S) { CPWAIT1(); } else { CPWAIT0(); }
        __syncthreads();
        if (s + 2 < S) NN_ISSUE(s + 2, (s + 2) % 3);
        mma_step<128>(Asb + buf * 2048, Bsb + buf * 4096, tn, tb, acc);
    }

    float* cp = Cpart + (size_t)blockIdx.y * ((size_t)B_ * N);
#pragma unroll
    for (int j = 0; j < 4; j++) {
        float2 u0 = up2(acc[j][0]), u1 = up2(acc[j][1]), u2 = up2(acc[j][2]), u3 = up2(acc[j][3]);
        int be = tb * 8 + 2 * j;
        *(float4*)&cp[(size_t)be * N + n0 + tn * 4]       = make_float4(u0.x, u1.x, u2.x, u3.x);
        *(float4*)&cp[(size_t)(be + 1) * N + n0 + tn * 4] = make_float4(u0.y, u1.y, u2.y, u3.y);
    }
}

__global__ __launch_bounds__(256) void gemm_nt(const float* __restrict__ AT,
                                               const float* __restrict__ Bt,
                                               float* __restrict__ Cpart,
                                               int P, int KD, int kchunk)
{
    extern __shared__ __align__(16) float sm[];
    float* Asb = sm;
    float* Wsb = sm + 3 * 2048;
    const int t = threadIdx.x, tn = t & 31, tb = t >> 5;
    const int p0 = blockIdx.x * 128;
    const int k0 = blockIdx.y * kchunk;
    const int kend = min(k0 + kchunk, KD);
    const int S = (kend - k0) / 32;

    ull acc[4][4];
#pragma unroll
    for (int j = 0; j < 4; j++)
#pragma unroll
        for (int i = 0; i < 4; i++) acc[j][i] = 0ull;

    const int ar = t >> 4, ac = (t & 15) * 4;
    const int lp = t >> 3, l8 = t & 7;
    float4 brg[4];

#define NT_ISSUEA(s, buf) { \
    int kb = k0 + (s) * 32; \
    float* Ab = Asb + (buf) * 2048; \
    cp16(s2u(Ab + ar * 64 + ac),        AT + (size_t)(kb + ar) * 64 + ac); \
    cp16(s2u(Ab + (ar + 16) * 64 + ac), AT + (size_t)(kb + ar + 16) * 64 + ac); \
    CPCOMMIT(); }

#define NT_LDGB(s) { \
    int kb = k0 + (s) * 32; \
    _Pragma("unroll") \
    for (int i = 0; i < 4; i++) { \
        int pg = p0 + lp + i * 32; \
        brg[i] = (pg < P) ? *(const float4*)(Bt + (size_t)pg * KD + kb + l8 * 4) \
                          : make_float4(0.f, 0.f, 0.f, 0.f); \
    } }

#define NT_STSB(buf) { \
    float* Wb = Wsb + (buf) * 4224; \
    _Pragma("unroll") \
    for (int i = 0; i < 4; i++) { \
        int pr = lp + i * 32; \
        Wb[(l8 * 4 + 0) * 132 + pr] = brg[i].x; \
        Wb[(l8 * 4 + 1) * 132 + pr] = brg[i].y; \
        Wb[(l8 * 4 + 2) * 132 + pr] = brg[i].z; \
        Wb[(l8 * 4 + 3) * 132 + pr] = brg[i].w; \
    } }

    if (S > 0) { NT_ISSUEA(0, 0); NT_LDGB(0); NT_STSB(0); }
    if (S > 1) NT_ISSUEA(1, 1);

    for (int s = 0; s < S; s++) {
        const int buf = s % 3;
        if (s + 1 < S) { CPWAIT1(); } else { CPWAIT0(); }
        __syncthreads();
        if (s + 2 < S) NT_ISSUEA(s + 2, (s + 2) % 3);
        if (s + 1 < S) NT_LDGB(s + 1);
        mma_step<132>(Asb + buf * 2048, Wsb + buf * 4224, tn, tb, acc);
        if (s + 1 < S) NT_STSB((s + 1) % 3);
    }

    float* cp = Cpart + (size_t)blockIdx.y * ((size_t)B_ * P);
    int p = p0 + tn * 4;
    if (p < P) {
#pragma unroll
        for (int j = 0; j < 4; j++) {
            float2 u0 = up2(acc[j][0]), u1 = up2(acc[j][1]), u2 = up2(acc[j][2]), u3 = up2(acc[j][3]);
            int be = tb * 8 + 2 * j;
            *(float4*)&cp[(size_t)be * P + p]       = make_float4(u0.x, u1.x, u2.x, u3.x);
            *(float4*)&cp[(size_t)(be + 1) * P + p] = make_float4(u0.y, u1.y, u2.y, u3.y);
        }
    }
}

__global__ void reduce_k(const float* __restrict__ part, float* __restrict__ out, int S, int len4)
{
    int i = blockIdx.x * blockDim.x + threadIdx.x;
    if (i >= len4) return;
    const float4* p4 = (const float4*)part;
    float4 s = p4[i];
    for (int ss = 1; ss < S; ss++) {
        float4 v = p4[(size_t)ss * len4 + i];
        s.x += v.x; s.y += v.y; s.z += v.z; s.w += v.w;
    }
    ((float4*)out)[i] = s;
}

__global__ void dmlnorm_k(const float* __restrict__ dml, float* __restrict__ dn)
{
    int w = threadIdx.x >> 5, lane = threadIdx.x & 31;
    int r = blockIdx.x * 8 + w;
    const float4* row = (const float4*)(dml + (size_t)r * DF);
    float s = 0.f;
#pragma unroll
    for (int i = 0; i < 4; i++) {
        float4 v = row[lane + i * 32];
        s += v.x*v.x + v.y*v.y + v.z*v.z + v.w*v.w;
    }
    for (int off = 16; off; off >>= 1) s += __shfl_down_sync(0xffffffffu, s, off);
    if (lane == 0) dn[r] = s;
}

__global__ void topk_k(const float* __restrict__ spart, const float* __restrict__ dnorm,
                       int* __restrict__ idxo)
{
    int b = blockIdx.x, t = threadIdx.x;
    __shared__ float sv[NDML];
    __shared__ ull red[256];
    for (int j = t; j < NDML; j += 256) {
        float dot = 0.f;
#pragma unroll
        for (int s = 0; s < 6; s++) dot += spart[(size_t)s * (B_ * NDML) + b * NDML + j];
        sv[j] = dnorm[j] - 2.f * dot;
    }
    __syncthreads();
    for (int r = 0; r < KNN; r++) {
        ull best = ~0ull;
        for (int j = t; j < NDML; j += 256) {
            uint u = __float_as_uint(sv[j]);
            u = (u & 0x80000000u) ? ~u : (u | 0x80000000u);
            ull key = ((ull)u << 32) | (uint)j;
            if (key < best) best = key;
        }
        red[t] = best;
        __syncthreads();
        for (int off = 128; off; off >>= 1) {
            if (t < off) { if (red[t + off] < red[t]) red[t] = red[t + off]; }
            __syncthreads();
        }
        int jw = (int)(red[0] & 0xffffffffu);
        if (t == 0) { idxo[b * KNN + r] = jw; sv[jw] = 3.4e38f; }
        __syncthreads();
    }
}

__global__ void embed_k(const float* __restrict__ x, const float* __restrict__ Wp,
                        const float* __restrict__ clst, float* __restrict__ E)
{
    int tok = blockIdx.x, b = blockIdx.y, h = threadIdx.x;
    if (tok == 0) { E[(size_t)b * P_ + h] = clst[h]; return; }
    __shared__ float pn[48];
    int pt = tok - 1, gr = pt >> 3, gc = pt & 7;
    if (h < 48) {
        int c = h >> 4, rem = h & 15, pr = rem >> 2, pc = rem & 3;
        float mean = (c == 0) ? 0.4914f : ((c == 1) ? 0.4822f : 0.4465f);
        float inv  = (c == 0) ? 4.048582995951417f : ((c == 1) ? 4.106776180698152f : 3.822629969418960f);
        float v = x[(((size_t)b * 3 + c) * 32 + gr * 4 + pr) * 32 + gc * 4 + pc];
        pn[h] = (v - mean) * inv;
    }
    __syncthreads();
    float acc = 0.f;
#pragma unroll
    for (int f = 0; f < 48; f++) acc += pn[f] * Wp[f * 384 + h];
    E[(size_t)b * P_ + tok * 384 + h] = acc;
}

__global__ __launch_bounds__(256) void scores_k(const float* __restrict__ tin,
                                                const float* __restrict__ OTin,
                                                const float* __restrict__ OTout,
                                                const int* __restrict__ idx,
                                                float* __restrict__ spart)
{
    int c = blockIdx.x, b = blockIdx.y, t = threadIdx.x;
    __shared__ __align__(16) float ts[2080];
    __shared__ int ids[10];
    __shared__ float warr[8];
    int base4 = (b * P_ + c * 2080) >> 2;
    const float4* t0 = (const float4*)tin + base4;
    for (int i = t; i < 520; i += 256) ((float4*)ts)[i] = t0[i];
    if (t < 10) ids[t] = idx[b * 10 + t];
    __syncthreads();

    float pacc[20];
#pragma unroll
    for (int n = 0; n < 20; n++) pacc[n] = 0.f;
#pragma unroll 1
    for (int n = 0; n < 20; n++) {
        const float* row = ((n < 10) ? OTin : OTout) + (size_t)ids[n % 10] * P_ + c * 2080;
        const float4* r4 = (const float4*)row;
        float s = 0.f;
        for (int i = t; i < 520; i += 256) {
            float4 v = r4[i]; float4 tt = ((float4*)ts)[i];
            s += v.x * tt.x + v.y * tt.y + v.z * tt.z + v.w * tt.w;
        }
        pacc[n] = s;
    }
    int lane = t & 31, wid = t >> 5;
    for (int n = 0; n < 20; n++) {
        float v = pacc[n];
        for (int off = 16; off; off >>= 1) v += __shfl_down_sync(0xffffffffu, v, off);
        if (lane == 0) warr[wid] = v;
        __syncthreads();
        if (t == 0) {
            float s = 0.f;
            for (int w = 0; w < 8; w++) s += warr[w];
            spart[((size_t)c * B_ + b) * 20 + n] = s;
        }
        __syncthreads();
    }
}

__global__ void softmax_k(const float* __restrict__ spart, float* __restrict__ attn)
{
    int b = blockIdx.x, n = threadIdx.x;
    float s = -3.4e38f;
    if (n < 20) {
        float acc = 0.f;
        for (int c = 0; c < 12; c++) acc += spart[((size_t)c * B_ + b) * 20 + n];
        s = acc * 0.022097086912079608f;
    }
    float m = s;
    for (int off = 16; off; off >>= 1) m = fmaxf(m, __shfl_xor_sync(0xffffffffu, m, off));
    float e = (n < 20) ? expf(s - m) : 0.f;
    float sum = e;
    for (int off = 16; off; off >>= 1) sum += __shfl_xor_sync(0xffffffffu, sum, off);
    if (n < 20) attn[b * 20 + n] = e / sum;
}

__global__ __launch_bounds__(256) void out_k(const float* __restrict__ OTin,
                                             const float* __restrict__ OTout,
                                             const int* __restrict__ idx,
                                             const float* __restrict__ attn,
                                             float* __restrict__ out)
{
    int c = blockIdx.x, b = blockIdx.y, t = threadIdx.x;
    __shared__ float a[20];
    __shared__ int ids[10];
    if (t < 20) a[t] = attn[b * 20 + t];
    if (t < 10) ids[t] = idx[b * 10 + t];
    __syncthreads();
    const float4* rows[20];
#pragma unroll
    for (int n = 0; n < 20; n++)
        rows[n] = (const float4*)(((n < 10) ? OTin : OTout) + (size_t)ids[n % 10] * P_ + c * 2080);
    float4* o4 = (float4*)(out + (size_t)b * P_ + c * 2080);
    for (int i = t; i < 520; i += 256) {
        float4 s = make_float4(0.f, 0.f, 0.f, 0.f);
#pragma unroll
        for (int n = 0; n < 20; n++) {
            float4 v = rows[n][i]; float an = a[n];
            s.x += an * v.x; s.y += an * v.y; s.z += an * v.z; s.w += an * v.w;
        }
        o4[i] = s;
    }
}

extern "C" void kernel_launch(void* const* d_in, const int* in_sizes, int n_in,
                              void* d_out, int out_size)
{
    const float* x     = (const float*)d_in[0];
    const float* dml   = (const float*)d_in[1];
    const float* OTin  = (const float*)d_in[2];
    const float* OTout = (const float*)d_in[3];
    const float* Wdml  = (const float*)d_in[4];
    const float* Wp    = (const float*)d_in[5];
    const float* clst  = (const float*)d_in[6];
    const float* Wq    = (const float*)d_in[7];
    const float* Wk    = (const float*)d_in[8];
    float* out = (float*)d_out;

    float *clspart, *cls, *dnorm, *scorepart, *embed, *qpart, *q, *tbuf, *spart, *attn;
    float *xT, *clsT;
    int* idx;
    cudaGetSymbolAddress((void**)&clspart,  g_clspart);
    cudaGetSymbolAddress((void**)&cls,      g_cls);
    cudaGetSymbolAddress((void**)&dnorm,    g_dmlnorm);
    cudaGetSymbolAddress((void**)&scorepart,g_scorepart);
    cudaGetSymbolAddress((void**)&idx,      g_idx);
    cudaGetSymbolAddress((void**)&embed,    g_embed);
    cudaGetSymbolAddress((void**)&qpart,    g_qpart);
    cudaGetSymbolAddress((void**)&q,        g_q);
    cudaGetSymbolAddress((void**)&tbuf,     g_t);
    cudaGetSymbolAddress((void**)&spart,    g_spart);
    cudaGetSymbolAddress((void**)&attn,     g_attn);
    cudaGetSymbolAddress((void**)&xT,       g_xT);
    cudaGetSymbolAddress((void**)&clsT,     g_clsT);

    const int nn_smem = (3 * 2048 + 3 * 4096) * 4;
    const int nt_smem = (3 * 2048 + 3 * 4224) * 4;
    const int tm_smem = 32768;
    cudaFuncSetAttribute(gemm_nn, cudaFuncAttributeMaxDynamicSharedMemorySize, nn_smem);
    cudaFuncSetAttribute(gemm_nt, cudaFuncAttributeMaxDynamicSharedMemorySize, nt_smem);
    cudaFuncSetAttribute(tmma_k, cudaFuncAttributeMaxDynamicSharedMemorySize, tm_smem);
    cudaFuncSetAttribute(qmma_k, cudaFuncAttributeMaxDynamicSharedMemorySize, tm_smem);

    dim3 t32(32, 32);
    embed_k<<<dim3(65, 64), 384>>>(x, Wp, clst, embed);                // 1
    dmlnorm_k<<<750, 256>>>(dml, dnorm);                               // 2
    transpose64<<<dim3(96, 2), t32>>>(x, xT, 3072);                    // 3
    qmma_k<<<dim3(32, 13), 256, tm_smem>>>(embed, Wq, qpart);          // 4 (profiled)
    reduce_k<<<128, 256>>>(qpart, q, 13, (B_ * DIM) / 4);              // 5
    tmma_k<<<390, 256, tm_smem>>>(q, Wk, tbuf);                        // 6
    // retrieval chain
    gemm_nn<<<dim3(4, 32), 256, nn_smem>>>(xT, Wdml, clspart, DF, 3072, 96);
    reduce_k<<<32, 256>>>(clspart, cls, 32, (B_ * DF) / 4);
    transpose64<<<dim3(16, 2), t32>>>(cls, clsT, DF);
    gemm_nt<<<dim3(47, 6), 256, nt_smem>>>(clsT, dml, scorepart, NDML, DF, 96);
    topk_k<<<64, 256>>>(scorepart, dnorm, idx);
    // attention readout
    scores_k<<<dim3(12, 64), 256>>>(tbuf, OTin, OTout, idx, spart);
    softmax_k<<<64, 32>>>(spart, attn);
    out_k<<<dim3(12, 64), 256>>>(OTin, OTout, idx, attn, out);
}